// round 1
// baseline (speedup 1.0000x reference)
#include <cuda_runtime.h>
#include <math.h>

#define BB 4
#define TT 2048
#define CC 1024
#define HH 16
#define DD 64
#define MM (BB*TT)   // 8192

// Scratch (device globals; no allocation allowed)
__device__ float g_q[MM * CC];
__device__ float g_k[MM * CC];
__device__ float g_v[MM * CC];
__device__ float g_attn[MM * CC];

// ---------------------------------------------------------------------------
// GEMM: C[M,N] = A[M,K] * W[N,K]^T   (both row-major, K-contiguous)
// BM=BN=128, BK=16, 256 threads, 8x8 register tile per thread.
// M=8192, N=1024, K=1024, all divisible by tile sizes -> no bounds checks.
// ---------------------------------------------------------------------------
__global__ __launch_bounds__(256) void gemm_atn(const float* __restrict__ A,
                                                const float* __restrict__ W,
                                                float* __restrict__ C)
{
    const int BM = 128, BN = 128, BK = 16;
    __shared__ float As[BK][BM];
    __shared__ float Bs[BK][BN];

    const int tid = threadIdx.x;
    const int tx = tid & 15;        // 0..15  (N direction)
    const int ty = tid >> 4;        // 0..15  (M direction)
    const int m0 = blockIdx.y * BM;
    const int n0 = blockIdx.x * BN;
    const int K = CC;

    float acc[8][8];
#pragma unroll
    for (int i = 0; i < 8; i++)
#pragma unroll
        for (int j = 0; j < 8; j++) acc[i][j] = 0.f;

    for (int k0 = 0; k0 < K; k0 += BK) {
#pragma unroll
        for (int it = 0; it < 2; it++) {
            int lin = tid + it * 256;
            int row = lin >> 2;          // 0..127
            int kc  = (lin & 3) * 4;     // 0,4,8,12
            float4 av = *(const float4*)&A[(size_t)(m0 + row) * K + k0 + kc];
            As[kc + 0][row] = av.x; As[kc + 1][row] = av.y;
            As[kc + 2][row] = av.z; As[kc + 3][row] = av.w;
            float4 bv = *(const float4*)&W[(size_t)(n0 + row) * K + k0 + kc];
            Bs[kc + 0][row] = bv.x; Bs[kc + 1][row] = bv.y;
            Bs[kc + 2][row] = bv.z; Bs[kc + 3][row] = bv.w;
        }
        __syncthreads();

#pragma unroll
        for (int k = 0; k < BK; k++) {
            float a[8], b[8];
#pragma unroll
            for (int i = 0; i < 8; i++) a[i] = As[k][ty * 8 + i];
#pragma unroll
            for (int j = 0; j < 8; j++) b[j] = Bs[k][tx * 8 + j];
#pragma unroll
            for (int i = 0; i < 8; i++)
#pragma unroll
                for (int j = 0; j < 8; j++)
                    acc[i][j] = fmaf(a[i], b[j], acc[i][j]);
        }
        __syncthreads();
    }

#pragma unroll
    for (int i = 0; i < 8; i++) {
        float4* p = (float4*)&C[(size_t)(m0 + ty * 8 + i) * CC + n0 + tx * 8];
        p[0] = make_float4(acc[i][0], acc[i][1], acc[i][2], acc[i][3]);
        p[1] = make_float4(acc[i][4], acc[i][5], acc[i][6], acc[i][7]);
    }
}

// ---------------------------------------------------------------------------
// Flash attention (causal), fp32. One block = one (b,h) x 64-query tile.
// 128 threads; thread (qg,kg) = (tid>>3, tid&7) owns a 4x8 score fragment.
// Q is pre-scaled by 1/sqrt(64)=0.125 at load. Online softmax with P staged
// through shared memory for the P*V product.
// ---------------------------------------------------------------------------
__global__ __launch_bounds__(128) void attn_kernel()
{
    extern __shared__ float sm[];
    const int QP = 65, KP = 65, VP = 64, PP = 65;
    float* Qs = sm;                  // 64 x 65
    float* Ks = Qs + 64 * QP;        // 64 x 65
    float* Vs = Ks + 64 * KP;        // 64 x 64
    float* Ps = Vs + 64 * VP;        // 64 x 65

    const int tid = threadIdx.x;
    const int qg = tid >> 3;         // 0..15 -> query rows qg*4..qg*4+3
    const int kg = tid & 7;          // 0..7  -> key cols / out dims kg*8..+7
    const int qtile = blockIdx.x;    // 0..31
    const int bh = blockIdx.y;       // 0..63
    const int b = bh / HH, h = bh % HH;
    const int q0 = qtile * 64;

    const float* qptr = g_q + (size_t)b * TT * CC + h * DD;
    const float* kptr = g_k + (size_t)b * TT * CC + h * DD;
    const float* vptr = g_v + (size_t)b * TT * CC + h * DD;

    // Load Q tile (pre-scaled)
#pragma unroll
    for (int it = 0; it < 8; it++) {
        int lin = tid + it * 128;
        int row = lin >> 4;          // 0..63
        int c4  = (lin & 15) * 4;    // 0..60
        float4 v4 = *(const float4*)&qptr[(size_t)(q0 + row) * CC + c4];
        Qs[row * QP + c4 + 0] = v4.x * 0.125f;
        Qs[row * QP + c4 + 1] = v4.y * 0.125f;
        Qs[row * QP + c4 + 2] = v4.z * 0.125f;
        Qs[row * QP + c4 + 3] = v4.w * 0.125f;
    }

    float m_i[4], l_i[4], o[4][8];
#pragma unroll
    for (int i = 0; i < 4; i++) {
        m_i[i] = -1e30f; l_i[i] = 0.f;
#pragma unroll
        for (int j = 0; j < 8; j++) o[i][j] = 0.f;
    }

    const int nkt = qtile + 1;
    for (int kt = 0; kt < nkt; kt++) {
        const int k0 = kt * 64;
        __syncthreads();  // previous iteration's readers of Ks/Vs/Ps done
        // Load K and V tiles
#pragma unroll
        for (int it = 0; it < 8; it++) {
            int lin = tid + it * 128;
            int row = lin >> 4;
            int c4  = (lin & 15) * 4;
            float4 kv = *(const float4*)&kptr[(size_t)(k0 + row) * CC + c4];
            Ks[row * KP + c4 + 0] = kv.x; Ks[row * KP + c4 + 1] = kv.y;
            Ks[row * KP + c4 + 2] = kv.z; Ks[row * KP + c4 + 3] = kv.w;
            float4 vv = *(const float4*)&vptr[(size_t)(k0 + row) * CC + c4];
            *(float4*)&Vs[row * VP + c4] = vv;
        }
        __syncthreads();

        // S = Q * K^T  (4x8 fragment per thread)
        float s[4][8];
#pragma unroll
        for (int i = 0; i < 4; i++)
#pragma unroll
            for (int j = 0; j < 8; j++) s[i][j] = 0.f;

#pragma unroll 8
        for (int kk = 0; kk < 64; kk++) {
            float a[4], bb[8];
#pragma unroll
            for (int i = 0; i < 4; i++) a[i] = Qs[(qg * 4 + i) * QP + kk];
#pragma unroll
            for (int j = 0; j < 8; j++) bb[j] = Ks[(kg * 8 + j) * KP + kk];
#pragma unroll
            for (int i = 0; i < 4; i++)
#pragma unroll
                for (int j = 0; j < 8; j++)
                    s[i][j] = fmaf(a[i], bb[j], s[i][j]);
        }

        // Causal mask on the diagonal tile
        if (kt == qtile) {
#pragma unroll
            for (int i = 0; i < 4; i++) {
                int qrow = q0 + qg * 4 + i;
#pragma unroll
                for (int j = 0; j < 8; j++) {
                    if (k0 + kg * 8 + j > qrow) s[i][j] = -1e30f;
                }
            }
        }

        // Online softmax update (8-lane row groups reduce via shuffles)
#pragma unroll
        for (int i = 0; i < 4; i++) {
            float mx = s[i][0];
#pragma unroll
            for (int j = 1; j < 8; j++) mx = fmaxf(mx, s[i][j]);
            mx = fmaxf(mx, __shfl_xor_sync(0xffffffffu, mx, 1));
            mx = fmaxf(mx, __shfl_xor_sync(0xffffffffu, mx, 2));
            mx = fmaxf(mx, __shfl_xor_sync(0xffffffffu, mx, 4));
            float mn = fmaxf(m_i[i], mx);
            float corr = __expf(m_i[i] - mn);
            m_i[i] = mn;
            float rs = 0.f;
#pragma unroll
            for (int j = 0; j < 8; j++) {
                float p = __expf(s[i][j] - mn);
                s[i][j] = p;
                rs += p;
            }
            rs += __shfl_xor_sync(0xffffffffu, rs, 1);
            rs += __shfl_xor_sync(0xffffffffu, rs, 2);
            rs += __shfl_xor_sync(0xffffffffu, rs, 4);
            l_i[i] = l_i[i] * corr + rs;
#pragma unroll
            for (int j = 0; j < 8; j++) o[i][j] *= corr;
        }

        // Stage P to shared
#pragma unroll
        for (int i = 0; i < 4; i++)
#pragma unroll
            for (int j = 0; j < 8; j++)
                Ps[(qg * 4 + i) * PP + kg * 8 + j] = s[i][j];
        __syncthreads();

        // O += P * V
#pragma unroll 8
        for (int kk = 0; kk < 64; kk++) {
            float p4[4], v8[8];
#pragma unroll
            for (int i = 0; i < 4; i++) p4[i] = Ps[(qg * 4 + i) * PP + kk];
#pragma unroll
            for (int j = 0; j < 8; j++) v8[j] = Vs[kk * VP + kg * 8 + j];
#pragma unroll
            for (int i = 0; i < 4; i++)
#pragma unroll
                for (int j = 0; j < 8; j++)
                    o[i][j] = fmaf(p4[i], v8[j], o[i][j]);
        }
    }

    // Epilogue: normalize and store to g_attn in [b, t, h*64+d] layout
    float* optr = g_attn + ((size_t)b * TT + q0) * CC + h * DD;
#pragma unroll
    for (int i = 0; i < 4; i++) {
        float inv = 1.f / l_i[i];
        float4 r0 = make_float4(o[i][0] * inv, o[i][1] * inv, o[i][2] * inv, o[i][3] * inv);
        float4 r1 = make_float4(o[i][4] * inv, o[i][5] * inv, o[i][6] * inv, o[i][7] * inv);
        float4* p = (float4*)&optr[(size_t)(qg * 4 + i) * CC + kg * 8];
        p[0] = r0; p[1] = r1;
    }
}

// ---------------------------------------------------------------------------
extern "C" void kernel_launch(void* const* d_in, const int* in_sizes, int n_in,
                              void* d_out, int out_size)
{
    const float* x   = (const float*)d_in[0];
    const float* W_Q = (const float*)d_in[1];
    const float* W_K = (const float*)d_in[2];
    const float* W_V = (const float*)d_in[3];
    const float* W_O = (const float*)d_in[4];
    float* out = (float*)d_out;

    float *q, *k, *v, *attn;
    cudaGetSymbolAddress((void**)&q,    g_q);
    cudaGetSymbolAddress((void**)&k,    g_k);
    cudaGetSymbolAddress((void**)&v,    g_v);
    cudaGetSymbolAddress((void**)&attn, g_attn);

    const int attn_smem = (64 * 65 * 3 + 64 * 64) * (int)sizeof(float);
    cudaFuncSetAttribute(attn_kernel,
                         cudaFuncAttributeMaxDynamicSharedMemorySize, attn_smem);

    dim3 ggrid(CC / 128, MM / 128);   // (8, 64)
    gemm_atn<<<ggrid, 256>>>(x, W_Q, q);
    gemm_atn<<<ggrid, 256>>>(x, W_K, k);
    gemm_atn<<<ggrid, 256>>>(x, W_V, v);

    dim3 agrid(TT / 64, BB * HH);     // (32, 64)
    attn_kernel<<<agrid, 128, attn_smem>>>();

    gemm_atn<<<ggrid, 256>>>(attn, W_O, out);
}

// round 3
// speedup vs baseline: 1.5451x; 1.5451x over previous
#include <cuda_runtime.h>
#include <cuda_bf16.h>
#include <math.h>
#include <stdint.h>

#define BB 4
#define TT 2048
#define CC 1024
#define HH 16
#define DD 64
#define MM (BB*TT)   // 8192

// ---------------------------------------------------------------------------
// Scratch (device globals; no allocation allowed)
// ---------------------------------------------------------------------------
__device__ float g_q[MM * CC];
__device__ float g_k[MM * CC];
__device__ float g_v[MM * CC];
__device__ float g_attn[MM * CC];
__device__ __nv_bfloat16 g_xhi[MM * CC];
__device__ __nv_bfloat16 g_xlo[MM * CC];
__device__ __nv_bfloat16 g_ahi[MM * CC];
__device__ __nv_bfloat16 g_alo[MM * CC];
__device__ __nv_bfloat16 g_whi[4 * CC * CC];
__device__ __nv_bfloat16 g_wlo[4 * CC * CC];

// ---------------------------------------------------------------------------
__device__ __forceinline__ uint32_t smem_u32(const void* p) {
    uint32_t a;
    asm("{ .reg .u64 t; cvta.to.shared.u64 t, %1; cvt.u32.u64 %0, t; }"
        : "=r"(a) : "l"(p));
    return a;
}

__device__ __forceinline__ void cp16(uint32_t dst, const void* src) {
    asm volatile("cp.async.cg.shared.global [%0], [%1], 16;"
                 :: "r"(dst), "l"(src) : "memory");
}
#define CP_COMMIT() asm volatile("cp.async.commit_group;" ::: "memory")
#define CP_WAIT(n)  asm volatile("cp.async.wait_group %0;" :: "n"(n) : "memory")

__device__ __forceinline__ void mma_bf16(float* d, const uint32_t* a, const uint32_t* b) {
    asm volatile(
        "mma.sync.aligned.m16n8k16.row.col.f32.bf16.bf16.f32 "
        "{%0,%1,%2,%3}, {%4,%5,%6,%7}, {%8,%9}, {%0,%1,%2,%3};"
        : "+f"(d[0]), "+f"(d[1]), "+f"(d[2]), "+f"(d[3])
        : "r"(a[0]), "r"(a[1]), "r"(a[2]), "r"(a[3]), "r"(b[0]), "r"(b[1]));
}

// ---------------------------------------------------------------------------
// fp32 -> bf16 hi/lo split (4 elems/thread, vectorized)
// ---------------------------------------------------------------------------
__global__ void split_kernel(const float* __restrict__ in,
                             __nv_bfloat16* __restrict__ hi,
                             __nv_bfloat16* __restrict__ lo, int n4)
{
    int i = blockIdx.x * blockDim.x + threadIdx.x;
    if (i >= n4) return;
    float4 v = ((const float4*)in)[i];
    __nv_bfloat16 h0 = __float2bfloat16(v.x);
    __nv_bfloat16 h1 = __float2bfloat16(v.y);
    __nv_bfloat16 h2 = __float2bfloat16(v.z);
    __nv_bfloat16 h3 = __float2bfloat16(v.w);
    __nv_bfloat16 l0 = __float2bfloat16(v.x - __bfloat162float(h0));
    __nv_bfloat16 l1 = __float2bfloat16(v.y - __bfloat162float(h1));
    __nv_bfloat16 l2 = __float2bfloat16(v.z - __bfloat162float(h2));
    __nv_bfloat16 l3 = __float2bfloat16(v.w - __bfloat162float(h3));
    __nv_bfloat162* hp = (__nv_bfloat162*)hi;
    __nv_bfloat162* lp = (__nv_bfloat162*)lo;
    hp[2 * i + 0] = __nv_bfloat162(h0, h1);
    hp[2 * i + 1] = __nv_bfloat162(h2, h3);
    lp[2 * i + 0] = __nv_bfloat162(l0, l1);
    lp[2 * i + 1] = __nv_bfloat162(l2, l3);
}

// ---------------------------------------------------------------------------
// bf16 mma.sync GEMM with hi/lo error compensation, fused 3-product K loop.
// C[M,N] = A[M,K] * W[N,K]^T ~= Ahi*Bhi + Ahi*Blo + Alo*Bhi
// Tile 128x128, BK=32, 256 threads (8 warps, 4Mx2N), warp tile 32x64.
// SMEM: 2 stages x 4 tiles (Ahi,Alo,Bhi,Blo) x 128 rows x 40 bf16 (80B rows).
// ---------------------------------------------------------------------------
#define ROWB 80u           // padded row bytes (40 bf16)
#define TILEB (128u*ROWB)  // 10240 B
#define STAGEB (4u*TILEB)  // 40960 B
#define NCHUNK (CC/32)     // 32

__global__ __launch_bounds__(256) void gemm_mma(
    const __nv_bfloat16* __restrict__ Ahi, const __nv_bfloat16* __restrict__ Alo,
    const __nv_bfloat16* __restrict__ Bhi, const __nv_bfloat16* __restrict__ Blo,
    float* __restrict__ C)
{
    extern __shared__ char smem[];
    const uint32_t sb = smem_u32(smem);
    const int tid  = threadIdx.x;
    const int lane = tid & 31;
    const int wid  = tid >> 5;
    const int wm   = wid >> 1;        // 0..3  (M)
    const int wn   = wid & 1;         // 0..1  (N)
    const int m0 = blockIdx.y * 128;
    const int n0 = blockIdx.x * 128;

    const __nv_bfloat16* srcs[4] = {
        Ahi + (size_t)m0 * CC, Alo + (size_t)m0 * CC,
        Bhi + (size_t)n0 * CC, Blo + (size_t)n0 * CC };

    // cp.async mapping: 8 chunks of 16B per thread covering 4 tiles
    auto issue_stage = [&](int chunk, int stage) {
        const int kc = chunk * 32;   // bf16 elems
        const uint32_t base = sb + (uint32_t)stage * STAGEB;
#pragma unroll
        for (int t = 0; t < 8; t++) {
            int lin  = tid + t * 256;        // 0..2047
            int tile = lin >> 9;             // 0..3
            int idx  = lin & 511;
            int row  = idx >> 2;             // 0..127
            int seg  = idx & 3;              // 0..3 (16B)
            uint32_t dst = base + (uint32_t)tile * TILEB + (uint32_t)row * ROWB + (uint32_t)seg * 16u;
            cp16(dst, srcs[tile] + (size_t)row * CC + kc + seg * 8);
        }
        CP_COMMIT();
    };

    float acc[2][8][4];
#pragma unroll
    for (int i = 0; i < 2; i++)
#pragma unroll
        for (int j = 0; j < 8; j++)
#pragma unroll
            for (int r = 0; r < 4; r++) acc[i][j][r] = 0.f;

    issue_stage(0, 0);

    for (int c = 0; c < NCHUNK; c++) {
        const int stage = c & 1;
        if (c + 1 < NCHUNK) { issue_stage(c + 1, stage ^ 1); CP_WAIT(1); }
        else                { CP_WAIT(0); }
        __syncthreads();

        const uint32_t base = sb + (uint32_t)stage * STAGEB;
        const uint32_t Aho = base;
        const uint32_t Alo_o = base + TILEB;
        const uint32_t Bho = base + 2u * TILEB;
        const uint32_t Blo_o = base + 3u * TILEB;

#pragma unroll
        for (int kk = 0; kk < 2; kk++) {        // two k16 steps per chunk
            const uint32_t kb = (uint32_t)kk * 32u + (uint32_t)(lane & 3) * 4u; // byte off in row
            // A fragments (hi and lo), frags fi = 0,1 (rows 16*fi)
            uint32_t ah[2][4], al[2][4];
#pragma unroll
            for (int fi = 0; fi < 2; fi++) {
                uint32_t r0 = (uint32_t)(wm * 32 + fi * 16 + (lane >> 2)) * ROWB + kb;
                uint32_t r1 = r0 + 8u * ROWB;
                asm volatile("ld.shared.b32 %0, [%1];" : "=r"(ah[fi][0]) : "r"(Aho + r0));
                asm volatile("ld.shared.b32 %0, [%1];" : "=r"(ah[fi][1]) : "r"(Aho + r1));
                asm volatile("ld.shared.b32 %0, [%1];" : "=r"(ah[fi][2]) : "r"(Aho + r0 + 16u));
                asm volatile("ld.shared.b32 %0, [%1];" : "=r"(ah[fi][3]) : "r"(Aho + r1 + 16u));
                asm volatile("ld.shared.b32 %0, [%1];" : "=r"(al[fi][0]) : "r"(Alo_o + r0));
                asm volatile("ld.shared.b32 %0, [%1];" : "=r"(al[fi][1]) : "r"(Alo_o + r1));
                asm volatile("ld.shared.b32 %0, [%1];" : "=r"(al[fi][2]) : "r"(Alo_o + r0 + 16u));
                asm volatile("ld.shared.b32 %0, [%1];" : "=r"(al[fi][3]) : "r"(Alo_o + r1 + 16u));
            }
            // B fragments and MMAs per n-frag
#pragma unroll
            for (int j = 0; j < 8; j++) {
                uint32_t nrow = (uint32_t)(wn * 64 + j * 8 + (lane >> 2)) * ROWB + kb;
                uint32_t bh[2], bl[2];
                asm volatile("ld.shared.b32 %0, [%1];" : "=r"(bh[0]) : "r"(Bho + nrow));
                asm volatile("ld.shared.b32 %0, [%1];" : "=r"(bh[1]) : "r"(Bho + nrow + 16u));
                asm volatile("ld.shared.b32 %0, [%1];" : "=r"(bl[0]) : "r"(Blo_o + nrow));
                asm volatile("ld.shared.b32 %0, [%1];" : "=r"(bl[1]) : "r"(Blo_o + nrow + 16u));
#pragma unroll
                for (int fi = 0; fi < 2; fi++) {
                    mma_bf16(acc[fi][j], ah[fi], bh);   // hi*hi
                    mma_bf16(acc[fi][j], ah[fi], bl);   // hi*lo
                    mma_bf16(acc[fi][j], al[fi], bh);   // lo*hi
                }
            }
        }
        __syncthreads();
    }

    // Epilogue: direct float2 stores
#pragma unroll
    for (int fi = 0; fi < 2; fi++) {
        int row0 = m0 + wm * 32 + fi * 16 + (lane >> 2);
#pragma unroll
        for (int j = 0; j < 8; j++) {
            int col = n0 + wn * 64 + j * 8 + (lane & 3) * 2;
            *(float2*)&C[(size_t)row0 * CC + col]       = make_float2(acc[fi][j][0], acc[fi][j][1]);
            *(float2*)&C[(size_t)(row0 + 8) * CC + col] = make_float2(acc[fi][j][2], acc[fi][j][3]);
        }
    }
}

// ---------------------------------------------------------------------------
// Flash attention (causal), fp32 — unchanged (passed round 1).
// ---------------------------------------------------------------------------
__global__ __launch_bounds__(128) void attn_kernel()
{
    extern __shared__ float sm[];
    const int QP = 65, KP = 65, VP = 64, PP = 65;
    float* Qs = sm;
    float* Ks = Qs + 64 * QP;
    float* Vs = Ks + 64 * KP;
    float* Ps = Vs + 64 * VP;

    const int tid = threadIdx.x;
    const int qg = tid >> 3;
    const int kg = tid & 7;
    const int qtile = blockIdx.x;
    const int bh = blockIdx.y;
    const int b = bh / HH, h = bh % HH;
    const int q0 = qtile * 64;

    const float* qptr = g_q + (size_t)b * TT * CC + h * DD;
    const float* kptr = g_k + (size_t)b * TT * CC + h * DD;
    const float* vptr = g_v + (size_t)b * TT * CC + h * DD;

#pragma unroll
    for (int it = 0; it < 8; it++) {
        int lin = tid + it * 128;
        int row = lin >> 4;
        int c4  = (lin & 15) * 4;
        float4 v4 = *(const float4*)&qptr[(size_t)(q0 + row) * CC + c4];
        Qs[row * QP + c4 + 0] = v4.x * 0.125f;
        Qs[row * QP + c4 + 1] = v4.y * 0.125f;
        Qs[row * QP + c4 + 2] = v4.z * 0.125f;
        Qs[row * QP + c4 + 3] = v4.w * 0.125f;
    }

    float m_i[4], l_i[4], o[4][8];
#pragma unroll
    for (int i = 0; i < 4; i++) {
        m_i[i] = -1e30f; l_i[i] = 0.f;
#pragma unroll
        for (int j = 0; j < 8; j++) o[i][j] = 0.f;
    }

    const int nkt = qtile + 1;
    for (int kt = 0; kt < nkt; kt++) {
        const int k0 = kt * 64;
        __syncthreads();
#pragma unroll
        for (int it = 0; it < 8; it++) {
            int lin = tid + it * 128;
            int row = lin >> 4;
            int c4  = (lin & 15) * 4;
            float4 kv = *(const float4*)&kptr[(size_t)(k0 + row) * CC + c4];
            Ks[row * KP + c4 + 0] = kv.x; Ks[row * KP + c4 + 1] = kv.y;
            Ks[row * KP + c4 + 2] = kv.z; Ks[row * KP + c4 + 3] = kv.w;
            float4 vv = *(const float4*)&vptr[(size_t)(k0 + row) * CC + c4];
            *(float4*)&Vs[row * VP + c4] = vv;
        }
        __syncthreads();

        float s[4][8];
#pragma unroll
        for (int i = 0; i < 4; i++)
#pragma unroll
            for (int j = 0; j < 8; j++) s[i][j] = 0.f;

#pragma unroll 8
        for (int kk = 0; kk < 64; kk++) {
            float a[4], bb[8];
#pragma unroll
            for (int i = 0; i < 4; i++) a[i] = Qs[(qg * 4 + i) * QP + kk];
#pragma unroll
            for (int j = 0; j < 8; j++) bb[j] = Ks[(kg * 8 + j) * KP + kk];
#pragma unroll
            for (int i = 0; i < 4; i++)
#pragma unroll
                for (int j = 0; j < 8; j++)
                    s[i][j] = fmaf(a[i], bb[j], s[i][j]);
        }

        if (kt == qtile) {
#pragma unroll
            for (int i = 0; i < 4; i++) {
                int qrow = q0 + qg * 4 + i;
#pragma unroll
                for (int j = 0; j < 8; j++) {
                    if (k0 + kg * 8 + j > qrow) s[i][j] = -1e30f;
                }
            }
        }

#pragma unroll
        for (int i = 0; i < 4; i++) {
            float mx = s[i][0];
#pragma unroll
            for (int j = 1; j < 8; j++) mx = fmaxf(mx, s[i][j]);
            mx = fmaxf(mx, __shfl_xor_sync(0xffffffffu, mx, 1));
            mx = fmaxf(mx, __shfl_xor_sync(0xffffffffu, mx, 2));
            mx = fmaxf(mx, __shfl_xor_sync(0xffffffffu, mx, 4));
            float mn = fmaxf(m_i[i], mx);
            float corr = __expf(m_i[i] - mn);
            m_i[i] = mn;
            float rs = 0.f;
#pragma unroll
            for (int j = 0; j < 8; j++) {
                float p = __expf(s[i][j] - mn);
                s[i][j] = p;
                rs += p;
            }
            rs += __shfl_xor_sync(0xffffffffu, rs, 1);
            rs += __shfl_xor_sync(0xffffffffu, rs, 2);
            rs += __shfl_xor_sync(0xffffffffu, rs, 4);
            l_i[i] = l_i[i] * corr + rs;
#pragma unroll
            for (int j = 0; j < 8; j++) o[i][j] *= corr;
        }

#pragma unroll
        for (int i = 0; i < 4; i++)
#pragma unroll
            for (int j = 0; j < 8; j++)
                Ps[(qg * 4 + i) * PP + kg * 8 + j] = s[i][j];
        __syncthreads();

#pragma unroll 8
        for (int kk = 0; kk < 64; kk++) {
            float p4[4], v8[8];
#pragma unroll
            for (int i = 0; i < 4; i++) p4[i] = Ps[(qg * 4 + i) * PP + kk];
#pragma unroll
            for (int j = 0; j < 8; j++) v8[j] = Vs[kk * VP + kg * 8 + j];
#pragma unroll
            for (int i = 0; i < 4; i++)
#pragma unroll
                for (int j = 0; j < 8; j++)
                    o[i][j] = fmaf(p4[i], v8[j], o[i][j]);
        }
    }

    float* optr = g_attn + ((size_t)b * TT + q0) * CC + h * DD;
#pragma unroll
    for (int i = 0; i < 4; i++) {
        float inv = 1.f / l_i[i];
        float4 r0 = make_float4(o[i][0] * inv, o[i][1] * inv, o[i][2] * inv, o[i][3] * inv);
        float4 r1 = make_float4(o[i][4] * inv, o[i][5] * inv, o[i][6] * inv, o[i][7] * inv);
        float4* p = (float4*)&optr[(size_t)(qg * 4 + i) * CC + kg * 8];
        p[0] = r0; p[1] = r1;
    }
}

// ---------------------------------------------------------------------------
extern "C" void kernel_launch(void* const* d_in, const int* in_sizes, int n_in,
                              void* d_out, int out_size)
{
    const float* x   = (const float*)d_in[0];
    const float* W_Q = (const float*)d_in[1];
    const float* W_K = (const float*)d_in[2];
    const float* W_V = (const float*)d_in[3];
    const float* W_O = (const float*)d_in[4];
    float* out = (float*)d_out;

    float *q, *k, *v, *attn;
    __nv_bfloat16 *xhi, *xlo, *ahi, *alo, *whi, *wlo;
    cudaGetSymbolAddress((void**)&q,    g_q);
    cudaGetSymbolAddress((void**)&k,    g_k);
    cudaGetSymbolAddress((void**)&v,    g_v);
    cudaGetSymbolAddress((void**)&attn, g_attn);
    cudaGetSymbolAddress((void**)&xhi,  g_xhi);
    cudaGetSymbolAddress((void**)&xlo,  g_xlo);
    cudaGetSymbolAddress((void**)&ahi,  g_ahi);
    cudaGetSymbolAddress((void**)&alo,  g_alo);
    cudaGetSymbolAddress((void**)&whi,  g_whi);
    cudaGetSymbolAddress((void**)&wlo,  g_wlo);

    const int gemm_smem = 2 * 40960;   // 81920
    cudaFuncSetAttribute(gemm_mma,
                         cudaFuncAttributeMaxDynamicSharedMemorySize, gemm_smem);
    const int attn_smem = (64 * 65 * 3 + 64 * 64) * (int)sizeof(float);
    cudaFuncSetAttribute(attn_kernel,
                         cudaFuncAttributeMaxDynamicSharedMemorySize, attn_smem);

    {
        int n4 = MM * CC / 4;
        split_kernel<<<(n4 + 255) / 256, 256>>>(x, xhi, xlo, n4);
        int w4 = CC * CC / 4;
        split_kernel<<<(w4 + 255) / 256, 256>>>(W_Q, whi + 0 * CC * CC, wlo + 0 * CC * CC, w4);
        split_kernel<<<(w4 + 255) / 256, 256>>>(W_K, whi + 1 * CC * CC, wlo + 1 * CC * CC, w4);
        split_kernel<<<(w4 + 255) / 256, 256>>>(W_V, whi + 2 * CC * CC, wlo + 2 * CC * CC, w4);
        split_kernel<<<(w4 + 255) / 256, 256>>>(W_O, whi + 3 * CC * CC, wlo + 3 * CC * CC, w4);
    }

    dim3 ggrid(CC / 128, MM / 128);   // (8, 64)
    gemm_mma<<<ggrid, 256, gemm_smem>>>(xhi, xlo, whi + 0 * CC * CC, wlo + 0 * CC * CC, q);
    gemm_mma<<<ggrid, 256, gemm_smem>>>(xhi, xlo, whi + 1 * CC * CC, wlo + 1 * CC * CC, k);
    gemm_mma<<<ggrid, 256, gemm_smem>>>(xhi, xlo, whi + 2 * CC * CC, wlo + 2 * CC * CC, v);

    dim3 agrid(TT / 64, BB * HH);     // (32, 64)
    attn_kernel<<<agrid, 128, attn_smem>>>();

    {
        int n4 = MM * CC / 4;
        split_kernel<<<(n4 + 255) / 256, 256>>>(attn, ahi, alo, n4);
    }
    gemm_mma<<<ggrid, 256, gemm_smem>>>(ahi, alo, whi + 3 * CC * CC, wlo + 3 * CC * CC, out);
}

// round 4
// speedup vs baseline: 2.4927x; 1.6133x over previous
#include <cuda_runtime.h>
#include <cuda_bf16.h>
#include <math.h>
#include <stdint.h>

#define BB 4
#define TT 2048
#define CC 1024
#define HH 16
#define DD 64
#define MM (BB*TT)   // 8192

// ---------------------------------------------------------------------------
// Scratch (device globals; no allocation allowed)
// ---------------------------------------------------------------------------
__device__ float g_q[MM * CC];
__device__ float g_k[MM * CC];
__device__ float g_v[MM * CC];
__device__ float g_attn[MM * CC];
__device__ __nv_bfloat16 g_xhi[MM * CC];
__device__ __nv_bfloat16 g_xlo[MM * CC];
__device__ __nv_bfloat16 g_ahi[MM * CC];
__device__ __nv_bfloat16 g_alo[MM * CC];
__device__ __nv_bfloat16 g_whi[4 * CC * CC];
__device__ __nv_bfloat16 g_wlo[4 * CC * CC];

// ---------------------------------------------------------------------------
__device__ __forceinline__ uint32_t smem_u32(const void* p) {
    uint32_t a;
    asm("{ .reg .u64 t; cvta.to.shared.u64 t, %1; cvt.u32.u64 %0, t; }"
        : "=r"(a) : "l"(p));
    return a;
}

__device__ __forceinline__ void cp16(uint32_t dst, const void* src) {
    asm volatile("cp.async.cg.shared.global [%0], [%1], 16;"
                 :: "r"(dst), "l"(src) : "memory");
}
#define CP_COMMIT() asm volatile("cp.async.commit_group;" ::: "memory")
#define CP_WAIT(n)  asm volatile("cp.async.wait_group %0;" :: "n"(n) : "memory")

__device__ __forceinline__ void mma_bf16(float* d, const uint32_t* a, const uint32_t* b) {
    asm volatile(
        "mma.sync.aligned.m16n8k16.row.col.f32.bf16.bf16.f32 "
        "{%0,%1,%2,%3}, {%4,%5,%6,%7}, {%8,%9}, {%0,%1,%2,%3};"
        : "+f"(d[0]), "+f"(d[1]), "+f"(d[2]), "+f"(d[3])
        : "r"(a[0]), "r"(a[1]), "r"(a[2]), "r"(a[3]), "r"(b[0]), "r"(b[1]));
}

__device__ __forceinline__ uint32_t lds32(uint32_t addr) {
    uint32_t v;
    asm volatile("ld.shared.b32 %0, [%1];" : "=r"(v) : "r"(addr));
    return v;
}

__device__ __forceinline__ uint32_t pack_bf16x2(float lo, float hi) {
    uint32_t r;
    asm("cvt.rn.bf16x2.f32 %0, %1, %2;" : "=r"(r) : "f"(hi), "f"(lo));
    return r;
}

// ---------------------------------------------------------------------------
// fp32 -> bf16 hi/lo split
// ---------------------------------------------------------------------------
__global__ void split_kernel(const float* __restrict__ in,
                             __nv_bfloat16* __restrict__ hi,
                             __nv_bfloat16* __restrict__ lo, int n4)
{
    int i = blockIdx.x * blockDim.x + threadIdx.x;
    if (i >= n4) return;
    float4 v = ((const float4*)in)[i];
    __nv_bfloat16 h0 = __float2bfloat16(v.x);
    __nv_bfloat16 h1 = __float2bfloat16(v.y);
    __nv_bfloat16 h2 = __float2bfloat16(v.z);
    __nv_bfloat16 h3 = __float2bfloat16(v.w);
    __nv_bfloat16 l0 = __float2bfloat16(v.x - __bfloat162float(h0));
    __nv_bfloat16 l1 = __float2bfloat16(v.y - __bfloat162float(h1));
    __nv_bfloat16 l2 = __float2bfloat16(v.z - __bfloat162float(h2));
    __nv_bfloat16 l3 = __float2bfloat16(v.w - __bfloat162float(h3));
    __nv_bfloat162* hp = (__nv_bfloat162*)hi;
    __nv_bfloat162* lp = (__nv_bfloat162*)lo;
    hp[2 * i + 0] = __nv_bfloat162(h0, h1);
    hp[2 * i + 1] = __nv_bfloat162(h2, h3);
    lp[2 * i + 0] = __nv_bfloat162(l0, l1);
    lp[2 * i + 1] = __nv_bfloat162(l2, l3);
}

// ---------------------------------------------------------------------------
// bf16 mma.sync GEMM with hi/lo error compensation (unchanged from round 3).
// ---------------------------------------------------------------------------
#define ROWB 80u
#define TILEB (128u*ROWB)
#define STAGEB (4u*TILEB)
#define NCHUNK (CC/32)

__global__ __launch_bounds__(256) void gemm_mma(
    const __nv_bfloat16* __restrict__ Ahi, const __nv_bfloat16* __restrict__ Alo,
    const __nv_bfloat16* __restrict__ Bhi, const __nv_bfloat16* __restrict__ Blo,
    float* __restrict__ C)
{
    extern __shared__ char smem[];
    const uint32_t sb = smem_u32(smem);
    const int tid  = threadIdx.x;
    const int lane = tid & 31;
    const int wid  = tid >> 5;
    const int wm   = wid >> 1;
    const int wn   = wid & 1;
    const int m0 = blockIdx.y * 128;
    const int n0 = blockIdx.x * 128;

    const __nv_bfloat16* srcs[4] = {
        Ahi + (size_t)m0 * CC, Alo + (size_t)m0 * CC,
        Bhi + (size_t)n0 * CC, Blo + (size_t)n0 * CC };

    auto issue_stage = [&](int chunk, int stage) {
        const int kc = chunk * 32;
        const uint32_t base = sb + (uint32_t)stage * STAGEB;
#pragma unroll
        for (int t = 0; t < 8; t++) {
            int lin  = tid + t * 256;
            int tile = lin >> 9;
            int idx  = lin & 511;
            int row  = idx >> 2;
            int seg  = idx & 3;
            uint32_t dst = base + (uint32_t)tile * TILEB + (uint32_t)row * ROWB + (uint32_t)seg * 16u;
            cp16(dst, srcs[tile] + (size_t)row * CC + kc + seg * 8);
        }
        CP_COMMIT();
    };

    float acc[2][8][4];
#pragma unroll
    for (int i = 0; i < 2; i++)
#pragma unroll
        for (int j = 0; j < 8; j++)
#pragma unroll
            for (int r = 0; r < 4; r++) acc[i][j][r] = 0.f;

    issue_stage(0, 0);

    for (int c = 0; c < NCHUNK; c++) {
        const int stage = c & 1;
        if (c + 1 < NCHUNK) { issue_stage(c + 1, stage ^ 1); CP_WAIT(1); }
        else                { CP_WAIT(0); }
        __syncthreads();

        const uint32_t base = sb + (uint32_t)stage * STAGEB;
        const uint32_t Aho = base;
        const uint32_t Alo_o = base + TILEB;
        const uint32_t Bho = base + 2u * TILEB;
        const uint32_t Blo_o = base + 3u * TILEB;

#pragma unroll
        for (int kk = 0; kk < 2; kk++) {
            const uint32_t kb = (uint32_t)kk * 32u + (uint32_t)(lane & 3) * 4u;
            uint32_t ah[2][4], al[2][4];
#pragma unroll
            for (int fi = 0; fi < 2; fi++) {
                uint32_t r0 = (uint32_t)(wm * 32 + fi * 16 + (lane >> 2)) * ROWB + kb;
                uint32_t r1 = r0 + 8u * ROWB;
                ah[fi][0] = lds32(Aho + r0);        ah[fi][1] = lds32(Aho + r1);
                ah[fi][2] = lds32(Aho + r0 + 16u);  ah[fi][3] = lds32(Aho + r1 + 16u);
                al[fi][0] = lds32(Alo_o + r0);      al[fi][1] = lds32(Alo_o + r1);
                al[fi][2] = lds32(Alo_o + r0 + 16u);al[fi][3] = lds32(Alo_o + r1 + 16u);
            }
#pragma unroll
            for (int j = 0; j < 8; j++) {
                uint32_t nrow = (uint32_t)(wn * 64 + j * 8 + (lane >> 2)) * ROWB + kb;
                uint32_t bh[2], bl[2];
                bh[0] = lds32(Bho + nrow);   bh[1] = lds32(Bho + nrow + 16u);
                bl[0] = lds32(Blo_o + nrow); bl[1] = lds32(Blo_o + nrow + 16u);
#pragma unroll
                for (int fi = 0; fi < 2; fi++) {
                    mma_bf16(acc[fi][j], ah[fi], bh);
                    mma_bf16(acc[fi][j], ah[fi], bl);
                    mma_bf16(acc[fi][j], al[fi], bh);
                }
            }
        }
        __syncthreads();
    }

#pragma unroll
    for (int fi = 0; fi < 2; fi++) {
        int row0 = m0 + wm * 32 + fi * 16 + (lane >> 2);
#pragma unroll
        for (int j = 0; j < 8; j++) {
            int col = n0 + wn * 64 + j * 8 + (lane & 3) * 2;
            *(float2*)&C[(size_t)row0 * CC + col]       = make_float2(acc[fi][j][0], acc[fi][j][1]);
            *(float2*)&C[(size_t)(row0 + 8) * CC + col] = make_float2(acc[fi][j][2], acc[fi][j][3]);
        }
    }
}

// ---------------------------------------------------------------------------
// Tensor-core flash attention (causal), bf16 hi/lo MMAs, fp32 softmax.
// Block = 128 threads (4 warps) handling 64 queries of one (b,h).
// Warp w owns query rows [w*16, w*16+16).
// SMEM (bf16, rows padded to 72 elems):
//   Qh,Ql [64][72] ; Kh,Kl [64][72] ; Vh,Vl [64][72] (V transposed: [d][k])
// ---------------------------------------------------------------------------
#define AP 72
#define ATILE (64 * AP)          // elems per buffer

__global__ __launch_bounds__(128) void attn_tc()
{
    extern __shared__ __nv_bfloat16 ash[];
    __nv_bfloat16* Qh = ash;
    __nv_bfloat16* Ql = Qh + ATILE;
    __nv_bfloat16* Kh = Ql + ATILE;
    __nv_bfloat16* Kl = Kh + ATILE;
    __nv_bfloat16* Vh = Kl + ATILE;
    __nv_bfloat16* Vl = Vh + ATILE;
    const uint32_t sQh = smem_u32(Qh), sQl = smem_u32(Ql);
    const uint32_t sKh = smem_u32(Kh), sKl = smem_u32(Kl);
    const uint32_t sVh = smem_u32(Vh), sVl = smem_u32(Vl);

    const int tid  = threadIdx.x;
    const int lane = tid & 31;
    const int w    = tid >> 5;
    const int qtile = blockIdx.x;
    const int bh = blockIdx.y;
    const int b = bh / HH, h = bh % HH;
    const int q0 = qtile * 64;

    const float* qptr = g_q + (size_t)b * TT * CC + h * DD;
    const float* kptr = g_k + (size_t)b * TT * CC + h * DD;
    const float* vptr = g_v + (size_t)b * TT * CC + h * DD;

    // ---- load Q (scaled by 1/8), split hi/lo ----
#pragma unroll
    for (int it = 0; it < 8; it++) {
        int lin = tid + it * 128;
        int row = lin >> 4;
        int c4  = (lin & 15) * 4;
        float4 v4 = *(const float4*)&qptr[(size_t)(q0 + row) * CC + c4];
        float f[4] = { v4.x * 0.125f, v4.y * 0.125f, v4.z * 0.125f, v4.w * 0.125f };
        __nv_bfloat16 hh[4], ll[4];
#pragma unroll
        for (int e = 0; e < 4; e++) {
            hh[e] = __float2bfloat16(f[e]);
            ll[e] = __float2bfloat16(f[e] - __bfloat162float(hh[e]));
        }
        *(__nv_bfloat162*)&Qh[row * AP + c4]     = __nv_bfloat162(hh[0], hh[1]);
        *(__nv_bfloat162*)&Qh[row * AP + c4 + 2] = __nv_bfloat162(hh[2], hh[3]);
        *(__nv_bfloat162*)&Ql[row * AP + c4]     = __nv_bfloat162(ll[0], ll[1]);
        *(__nv_bfloat162*)&Ql[row * AP + c4 + 2] = __nv_bfloat162(ll[2], ll[3]);
    }
    __syncthreads();

    // ---- hoist Q A-fragments (invariant over key loop): 4 k-steps ----
    uint32_t aqh[4][4], aql[4][4];
    {
        const uint32_t kb = (uint32_t)(lane & 3) * 4u;
        const uint32_t r0 = (uint32_t)(w * 16 + (lane >> 2)) * (AP * 2) + kb;
        const uint32_t r1 = r0 + 8u * (AP * 2);
#pragma unroll
        for (int s = 0; s < 4; s++) {
            uint32_t ko = (uint32_t)s * 32u;
            aqh[s][0] = lds32(sQh + r0 + ko);       aqh[s][1] = lds32(sQh + r1 + ko);
            aqh[s][2] = lds32(sQh + r0 + ko + 16u); aqh[s][3] = lds32(sQh + r1 + ko + 16u);
            aql[s][0] = lds32(sQl + r0 + ko);       aql[s][1] = lds32(sQl + r1 + ko);
            aql[s][2] = lds32(sQl + r0 + ko + 16u); aql[s][3] = lds32(sQl + r1 + ko + 16u);
        }
    }

    float m0r = -1e30f, m1r = -1e30f, l0r = 0.f, l1r = 0.f;
    float ofr[8][4];
#pragma unroll
    for (int j = 0; j < 8; j++)
#pragma unroll
        for (int r = 0; r < 4; r++) ofr[j][r] = 0.f;

    const int r0g = q0 + w * 16 + (lane >> 2);
    const int r1g = r0g + 8;

    const int nkt = qtile + 1;
    for (int kt = 0; kt < nkt; kt++) {
        const int k0 = kt * 64;
        __syncthreads();
        // ---- load K (straight) and V (transposed), split hi/lo ----
#pragma unroll
        for (int it = 0; it < 8; it++) {
            int lin = tid + it * 128;
            int row = lin >> 4;
            int c4  = (lin & 15) * 4;
            float4 kv = *(const float4*)&kptr[(size_t)(k0 + row) * CC + c4];
            float kf[4] = { kv.x, kv.y, kv.z, kv.w };
            __nv_bfloat16 khh[4], kll[4];
#pragma unroll
            for (int e = 0; e < 4; e++) {
                khh[e] = __float2bfloat16(kf[e]);
                kll[e] = __float2bfloat16(kf[e] - __bfloat162float(khh[e]));
            }
            *(__nv_bfloat162*)&Kh[row * AP + c4]     = __nv_bfloat162(khh[0], khh[1]);
            *(__nv_bfloat162*)&Kh[row * AP + c4 + 2] = __nv_bfloat162(khh[2], khh[3]);
            *(__nv_bfloat162*)&Kl[row * AP + c4]     = __nv_bfloat162(kll[0], kll[1]);
            *(__nv_bfloat162*)&Kl[row * AP + c4 + 2] = __nv_bfloat162(kll[2], kll[3]);

            float4 vv = *(const float4*)&vptr[(size_t)(k0 + row) * CC + c4];
            float vf[4] = { vv.x, vv.y, vv.z, vv.w };
#pragma unroll
            for (int e = 0; e < 4; e++) {
                __nv_bfloat16 vh = __float2bfloat16(vf[e]);
                __nv_bfloat16 vl = __float2bfloat16(vf[e] - __bfloat162float(vh));
                Vh[(c4 + e) * AP + row] = vh;   // transposed: [d][k]
                Vl[(c4 + e) * AP + row] = vl;
            }
        }
        __syncthreads();

        // ---- S = Q*K^T (hi/lo compensated) ----
        float sfr[8][4];
#pragma unroll
        for (int j = 0; j < 8; j++)
#pragma unroll
            for (int r = 0; r < 4; r++) sfr[j][r] = 0.f;

        const uint32_t kb = (uint32_t)(lane & 3) * 4u;
#pragma unroll
        for (int j = 0; j < 8; j++) {
            uint32_t nrow = (uint32_t)(j * 8 + (lane >> 2)) * (AP * 2) + kb;
#pragma unroll
            for (int s = 0; s < 4; s++) {
                uint32_t ko = (uint32_t)s * 32u;
                uint32_t bhf[2], blf[2];
                bhf[0] = lds32(sKh + nrow + ko); bhf[1] = lds32(sKh + nrow + ko + 16u);
                blf[0] = lds32(sKl + nrow + ko); blf[1] = lds32(sKl + nrow + ko + 16u);
                mma_bf16(sfr[j], aqh[s], bhf);
                mma_bf16(sfr[j], aqh[s], blf);
                mma_bf16(sfr[j], aql[s], bhf);
            }
        }

        // ---- causal mask on diagonal tile ----
        if (kt == qtile) {
#pragma unroll
            for (int j = 0; j < 8; j++) {
                int cbase = k0 + j * 8 + 2 * (lane & 3);
                if (cbase > r0g)     sfr[j][0] = -1e30f;
                if (cbase + 1 > r0g) sfr[j][1] = -1e30f;
                if (cbase > r1g)     sfr[j][2] = -1e30f;
                if (cbase + 1 > r1g) sfr[j][3] = -1e30f;
            }
        }

        // ---- online softmax ----
        float mx0 = -1e30f, mx1 = -1e30f;
#pragma unroll
        for (int j = 0; j < 8; j++) {
            mx0 = fmaxf(mx0, fmaxf(sfr[j][0], sfr[j][1]));
            mx1 = fmaxf(mx1, fmaxf(sfr[j][2], sfr[j][3]));
        }
        mx0 = fmaxf(mx0, __shfl_xor_sync(0xffffffffu, mx0, 1));
        mx0 = fmaxf(mx0, __shfl_xor_sync(0xffffffffu, mx0, 2));
        mx1 = fmaxf(mx1, __shfl_xor_sync(0xffffffffu, mx1, 1));
        mx1 = fmaxf(mx1, __shfl_xor_sync(0xffffffffu, mx1, 2));

        float mn0 = fmaxf(m0r, mx0), mn1 = fmaxf(m1r, mx1);
        float corr0 = __expf(m0r - mn0), corr1 = __expf(m1r - mn1);
        m0r = mn0; m1r = mn1;

        float rs0 = 0.f, rs1 = 0.f;
#pragma unroll
        for (int j = 0; j < 8; j++) {
            sfr[j][0] = __expf(sfr[j][0] - mn0);
            sfr[j][1] = __expf(sfr[j][1] - mn0);
            sfr[j][2] = __expf(sfr[j][2] - mn1);
            sfr[j][3] = __expf(sfr[j][3] - mn1);
            rs0 += sfr[j][0] + sfr[j][1];
            rs1 += sfr[j][2] + sfr[j][3];
        }
        rs0 += __shfl_xor_sync(0xffffffffu, rs0, 1);
        rs0 += __shfl_xor_sync(0xffffffffu, rs0, 2);
        rs1 += __shfl_xor_sync(0xffffffffu, rs1, 1);
        rs1 += __shfl_xor_sync(0xffffffffu, rs1, 2);
        l0r = l0r * corr0 + rs0;
        l1r = l1r * corr1 + rs1;

#pragma unroll
        for (int j = 0; j < 8; j++) {
            ofr[j][0] *= corr0; ofr[j][1] *= corr0;
            ofr[j][2] *= corr1; ofr[j][3] *= corr1;
        }

        // ---- pack P to bf16 hi/lo A-fragments ----
        uint32_t pah[4][4], pal[4][4];
#pragma unroll
        for (int s = 0; s < 4; s++) {
            const int ja = 2 * s, jb = 2 * s + 1;
            float p[8] = { sfr[ja][0], sfr[ja][1], sfr[ja][2], sfr[ja][3],
                           sfr[jb][0], sfr[jb][1], sfr[jb][2], sfr[jb][3] };
            __nv_bfloat16 phh[8];
            float pl[8];
#pragma unroll
            for (int e = 0; e < 8; e++) {
                phh[e] = __float2bfloat16(p[e]);
                pl[e] = p[e] - __bfloat162float(phh[e]);
            }
            pah[s][0] = pack_bf16x2(__bfloat162float(phh[0]), __bfloat162float(phh[1]));
            pah[s][1] = pack_bf16x2(__bfloat162float(phh[2]), __bfloat162float(phh[3]));
            pah[s][2] = pack_bf16x2(__bfloat162float(phh[4]), __bfloat162float(phh[5]));
            pah[s][3] = pack_bf16x2(__bfloat162float(phh[6]), __bfloat162float(phh[7]));
            pal[s][0] = pack_bf16x2(pl[0], pl[1]);
            pal[s][1] = pack_bf16x2(pl[2], pl[3]);
            pal[s][2] = pack_bf16x2(pl[4], pl[5]);
            pal[s][3] = pack_bf16x2(pl[6], pl[7]);
        }

        // ---- O += P*V (hi/lo compensated) ----
#pragma unroll
        for (int j = 0; j < 8; j++) {
            uint32_t drow = (uint32_t)(j * 8 + (lane >> 2)) * (AP * 2) + kb;
#pragma unroll
            for (int s = 0; s < 4; s++) {
                uint32_t ko = (uint32_t)s * 32u;
                uint32_t bvh[2], bvl[2];
                bvh[0] = lds32(sVh + drow + ko); bvh[1] = lds32(sVh + drow + ko + 16u);
                bvl[0] = lds32(sVl + drow + ko); bvl[1] = lds32(sVl + drow + ko + 16u);
                mma_bf16(ofr[j], pah[s], bvh);
                mma_bf16(ofr[j], pah[s], bvl);
                mma_bf16(ofr[j], pal[s], bvh);
            }
        }
    }

    // ---- epilogue ----
    float inv0 = 1.f / l0r, inv1 = 1.f / l1r;
    float* optr = g_attn + (size_t)b * TT * CC + h * DD;
#pragma unroll
    for (int j = 0; j < 8; j++) {
        int col = j * 8 + 2 * (lane & 3);
        *(float2*)&optr[(size_t)r0g * CC + col] = make_float2(ofr[j][0] * inv0, ofr[j][1] * inv0);
        *(float2*)&optr[(size_t)r1g * CC + col] = make_float2(ofr[j][2] * inv1, ofr[j][3] * inv1);
    }
}

// ---------------------------------------------------------------------------
extern "C" void kernel_launch(void* const* d_in, const int* in_sizes, int n_in,
                              void* d_out, int out_size)
{
    const float* x   = (const float*)d_in[0];
    const float* W_Q = (const float*)d_in[1];
    const float* W_K = (const float*)d_in[2];
    const float* W_V = (const float*)d_in[3];
    const float* W_O = (const float*)d_in[4];
    float* out = (float*)d_out;

    float *q, *k, *v, *attn;
    __nv_bfloat16 *xhi, *xlo, *ahi, *alo, *whi, *wlo;
    cudaGetSymbolAddress((void**)&q,    g_q);
    cudaGetSymbolAddress((void**)&k,    g_k);
    cudaGetSymbolAddress((void**)&v,    g_v);
    cudaGetSymbolAddress((void**)&attn, g_attn);
    cudaGetSymbolAddress((void**)&xhi,  g_xhi);
    cudaGetSymbolAddress((void**)&xlo,  g_xlo);
    cudaGetSymbolAddress((void**)&ahi,  g_ahi);
    cudaGetSymbolAddress((void**)&alo,  g_alo);
    cudaGetSymbolAddress((void**)&whi,  g_whi);
    cudaGetSymbolAddress((void**)&wlo,  g_wlo);

    const int gemm_smem = 2 * 40960;
    cudaFuncSetAttribute(gemm_mma,
                         cudaFuncAttributeMaxDynamicSharedMemorySize, gemm_smem);
    const int attn_smem = 6 * ATILE * (int)sizeof(__nv_bfloat16);   // 55296
    cudaFuncSetAttribute(attn_tc,
                         cudaFuncAttributeMaxDynamicSharedMemorySize, attn_smem);

    {
        int n4 = MM * CC / 4;
        split_kernel<<<(n4 + 255) / 256, 256>>>(x, xhi, xlo, n4);
        int w4 = CC * CC / 4;
        split_kernel<<<(w4 + 255) / 256, 256>>>(W_Q, whi + 0 * CC * CC, wlo + 0 * CC * CC, w4);
        split_kernel<<<(w4 + 255) / 256, 256>>>(W_K, whi + 1 * CC * CC, wlo + 1 * CC * CC, w4);
        split_kernel<<<(w4 + 255) / 256, 256>>>(W_V, whi + 2 * CC * CC, wlo + 2 * CC * CC, w4);
        split_kernel<<<(w4 + 255) / 256, 256>>>(W_O, whi + 3 * CC * CC, wlo + 3 * CC * CC, w4);
    }

    dim3 ggrid(CC / 128, MM / 128);
    gemm_mma<<<ggrid, 256, gemm_smem>>>(xhi, xlo, whi + 0 * CC * CC, wlo + 0 * CC * CC, q);
    gemm_mma<<<ggrid, 256, gemm_smem>>>(xhi, xlo, whi + 1 * CC * CC, wlo + 1 * CC * CC, k);
    gemm_mma<<<ggrid, 256, gemm_smem>>>(xhi, xlo, whi + 2 * CC * CC, wlo + 2 * CC * CC, v);

    dim3 agrid(TT / 64, BB * HH);
    attn_tc<<<agrid, 128, attn_smem>>>();

    {
        int n4 = MM * CC / 4;
        split_kernel<<<(n4 + 255) / 256, 256>>>(attn, ahi, alo, n4);
    }
    gemm_mma<<<ggrid, 256, gemm_smem>>>(ahi, alo, whi + 3 * CC * CC, wlo + 3 * CC * CC, out);
}

// round 5
// speedup vs baseline: 2.5336x; 1.0164x over previous
#include <cuda_runtime.h>
#include <cuda_bf16.h>
#include <math.h>
#include <stdint.h>

#define BB 4
#define TT 2048
#define CC 1024
#define HH 16
#define DD 64
#define MM (BB*TT)   // 8192

// ---------------------------------------------------------------------------
// Scratch (device globals; no allocation allowed)
// ---------------------------------------------------------------------------
__device__ float g_q[MM * CC];
__device__ float g_k[MM * CC];
__device__ float g_v[MM * CC];
__device__ __nv_bfloat16 g_xhi[MM * CC];
__device__ __nv_bfloat16 g_xlo[MM * CC];
__device__ __nv_bfloat16 g_ahi[MM * CC];
__device__ __nv_bfloat16 g_alo[MM * CC];
__device__ __nv_bfloat16 g_whi[4 * CC * CC];
__device__ __nv_bfloat16 g_wlo[4 * CC * CC];

// ---------------------------------------------------------------------------
__device__ __forceinline__ uint32_t smem_u32(const void* p) {
    uint32_t a;
    asm("{ .reg .u64 t; cvta.to.shared.u64 t, %1; cvt.u32.u64 %0, t; }"
        : "=r"(a) : "l"(p));
    return a;
}

__device__ __forceinline__ void cp16(uint32_t dst, const void* src) {
    asm volatile("cp.async.cg.shared.global [%0], [%1], 16;"
                 :: "r"(dst), "l"(src) : "memory");
}
#define CP_COMMIT() asm volatile("cp.async.commit_group;" ::: "memory")
#define CP_WAIT(n)  asm volatile("cp.async.wait_group %0;" :: "n"(n) : "memory")

__device__ __forceinline__ void mma_bf16(float* d, const uint32_t* a, const uint32_t* b) {
    asm volatile(
        "mma.sync.aligned.m16n8k16.row.col.f32.bf16.bf16.f32 "
        "{%0,%1,%2,%3}, {%4,%5,%6,%7}, {%8,%9}, {%0,%1,%2,%3};"
        : "+f"(d[0]), "+f"(d[1]), "+f"(d[2]), "+f"(d[3])
        : "r"(a[0]), "r"(a[1]), "r"(a[2]), "r"(a[3]), "r"(b[0]), "r"(b[1]));
}

__device__ __forceinline__ void ldm_x4(uint32_t* r, uint32_t addr) {
    asm volatile("ldmatrix.sync.aligned.m8n8.x4.shared.b16 {%0,%1,%2,%3}, [%4];"
                 : "=r"(r[0]), "=r"(r[1]), "=r"(r[2]), "=r"(r[3]) : "r"(addr));
}
__device__ __forceinline__ void ldm_x2(uint32_t* r, uint32_t addr) {
    asm volatile("ldmatrix.sync.aligned.m8n8.x2.shared.b16 {%0,%1}, [%2];"
                 : "=r"(r[0]), "=r"(r[1]) : "r"(addr));
}

__device__ __forceinline__ uint32_t lds32(uint32_t addr) {
    uint32_t v;
    asm volatile("ld.shared.b32 %0, [%1];" : "=r"(v) : "r"(addr));
    return v;
}

__device__ __forceinline__ uint32_t pack_bf16x2(float lo, float hi) {
    uint32_t r;
    asm("cvt.rn.bf16x2.f32 %0, %1, %2;" : "=r"(r) : "f"(hi), "f"(lo));
    return r;
}

// ---------------------------------------------------------------------------
// fp32 -> bf16 hi/lo split
// ---------------------------------------------------------------------------
__global__ void split_kernel(const float* __restrict__ in,
                             __nv_bfloat16* __restrict__ hi,
                             __nv_bfloat16* __restrict__ lo, int n4)
{
    int i = blockIdx.x * blockDim.x + threadIdx.x;
    if (i >= n4) return;
    float4 v = ((const float4*)in)[i];
    __nv_bfloat16 h0 = __float2bfloat16(v.x);
    __nv_bfloat16 h1 = __float2bfloat16(v.y);
    __nv_bfloat16 h2 = __float2bfloat16(v.z);
    __nv_bfloat16 h3 = __float2bfloat16(v.w);
    __nv_bfloat16 l0 = __float2bfloat16(v.x - __bfloat162float(h0));
    __nv_bfloat16 l1 = __float2bfloat16(v.y - __bfloat162float(h1));
    __nv_bfloat16 l2 = __float2bfloat16(v.z - __bfloat162float(h2));
    __nv_bfloat16 l3 = __float2bfloat16(v.w - __bfloat162float(h3));
    __nv_bfloat162* hp = (__nv_bfloat162*)hi;
    __nv_bfloat162* lp = (__nv_bfloat162*)lo;
    hp[2 * i + 0] = __nv_bfloat162(h0, h1);
    hp[2 * i + 1] = __nv_bfloat162(h2, h3);
    lp[2 * i + 0] = __nv_bfloat162(l0, l1);
    lp[2 * i + 1] = __nv_bfloat162(l2, l3);
}

// ---------------------------------------------------------------------------
// Core GEMM tile routine: C_tile[128,128] = A[M,K] x W[N,K]^T (hi/lo comp.)
// 256 threads, BK=32 double-buffered cp.async, ldmatrix fragment loads.
// ---------------------------------------------------------------------------
#define ROWB 80u
#define TILEB (128u*ROWB)
#define STAGEB (4u*TILEB)
#define NCHUNK (CC/32)

__device__ __forceinline__ void gemm_tile(
    const __nv_bfloat16* __restrict__ Ahi, const __nv_bfloat16* __restrict__ Alo,
    const __nv_bfloat16* __restrict__ Bhi, const __nv_bfloat16* __restrict__ Blo,
    float* __restrict__ C, int m0, int n0, char* smem)
{
    const uint32_t sb = smem_u32(smem);
    const int tid  = threadIdx.x;
    const int lane = tid & 31;
    const int wid  = tid >> 5;
    const int wm   = wid >> 1;
    const int wn   = wid & 1;

    const __nv_bfloat16* srcs[4] = {
        Ahi + (size_t)m0 * CC, Alo + (size_t)m0 * CC,
        Bhi + (size_t)n0 * CC, Blo + (size_t)n0 * CC };

    auto issue_stage = [&](int chunk, int stage) {
        const int kc = chunk * 32;
        const uint32_t base = sb + (uint32_t)stage * STAGEB;
#pragma unroll
        for (int t = 0; t < 8; t++) {
            int lin  = tid + t * 256;
            int tile = lin >> 9;
            int idx  = lin & 511;
            int row  = idx >> 2;
            int seg  = idx & 3;
            uint32_t dst = base + (uint32_t)tile * TILEB + (uint32_t)row * ROWB + (uint32_t)seg * 16u;
            cp16(dst, srcs[tile] + (size_t)row * CC + kc + seg * 8);
        }
        CP_COMMIT();
    };

    float acc[2][8][4];
#pragma unroll
    for (int i = 0; i < 2; i++)
#pragma unroll
        for (int j = 0; j < 8; j++)
#pragma unroll
            for (int r = 0; r < 4; r++) acc[i][j][r] = 0.f;

    issue_stage(0, 0);

    // ldmatrix lane-address components
    const uint32_t a_row  = (uint32_t)(lane & 15);          // row within 16-row frag
    const uint32_t a_koff = (uint32_t)(lane >> 4) * 16u;    // 0 or 16 bytes
    const uint32_t b_row  = (uint32_t)(lane & 7);           // n row within 8
    const uint32_t b_koff = (uint32_t)((lane >> 3) & 1) * 16u;

    for (int c = 0; c < NCHUNK; c++) {
        const int stage = c & 1;
        if (c + 1 < NCHUNK) { issue_stage(c + 1, stage ^ 1); CP_WAIT(1); }
        else                { CP_WAIT(0); }
        __syncthreads();

        const uint32_t base = sb + (uint32_t)stage * STAGEB;
        const uint32_t Aho   = base;
        const uint32_t Alo_o = base + TILEB;
        const uint32_t Bho   = base + 2u * TILEB;
        const uint32_t Blo_o = base + 3u * TILEB;

#pragma unroll
        for (int kk = 0; kk < 2; kk++) {
            const uint32_t ko = (uint32_t)kk * 32u;
            uint32_t ah[2][4], al[2][4];
#pragma unroll
            for (int fi = 0; fi < 2; fi++) {
                uint32_t ra = (uint32_t)(wm * 32 + fi * 16) * ROWB + a_row * ROWB + ko + a_koff;
                ldm_x4(ah[fi], Aho + ra);
                ldm_x4(al[fi], Alo_o + ra);
            }
#pragma unroll
            for (int j = 0; j < 8; j++) {
                uint32_t rb = (uint32_t)(wn * 64 + j * 8) * ROWB + b_row * ROWB + ko + b_koff;
                uint32_t bh[2], bl[2];
                ldm_x2(bh, Bho + rb);
                ldm_x2(bl, Blo_o + rb);
#pragma unroll
                for (int fi = 0; fi < 2; fi++) {
                    mma_bf16(acc[fi][j], ah[fi], bh);
                    mma_bf16(acc[fi][j], ah[fi], bl);
                    mma_bf16(acc[fi][j], al[fi], bh);
                }
            }
        }
        __syncthreads();
    }

#pragma unroll
    for (int fi = 0; fi < 2; fi++) {
        int row0 = m0 + wm * 32 + fi * 16 + (lane >> 2);
#pragma unroll
        for (int j = 0; j < 8; j++) {
            int col = n0 + wn * 64 + j * 8 + (lane & 3) * 2;
            *(float2*)&C[(size_t)row0 * CC + col]       = make_float2(acc[fi][j][0], acc[fi][j][1]);
            *(float2*)&C[(size_t)(row0 + 8) * CC + col] = make_float2(acc[fi][j][2], acc[fi][j][3]);
        }
    }
}

// Fused QKV: grid.x in [0,24): wsel = x>>3 selects weight/output, n0 = (x&7)*128
__global__ __launch_bounds__(256, 2) void gemm_qkv(
    const __nv_bfloat16* __restrict__ xhi, const __nv_bfloat16* __restrict__ xlo,
    const __nv_bfloat16* __restrict__ whi, const __nv_bfloat16* __restrict__ wlo,
    float* __restrict__ q, float* __restrict__ k, float* __restrict__ v)
{
    extern __shared__ char smem[];
    const int wsel = blockIdx.x >> 3;
    const int n0 = (blockIdx.x & 7) * 128;
    const int m0 = blockIdx.y * 128;
    float* outs[3] = { q, k, v };
    gemm_tile(xhi, xlo,
              whi + (size_t)wsel * CC * CC, wlo + (size_t)wsel * CC * CC,
              outs[wsel], m0, n0, smem);
}

// Single GEMM (output projection)
__global__ __launch_bounds__(256, 2) void gemm_one(
    const __nv_bfloat16* __restrict__ Ahi, const __nv_bfloat16* __restrict__ Alo,
    const __nv_bfloat16* __restrict__ Bhi, const __nv_bfloat16* __restrict__ Blo,
    float* __restrict__ C)
{
    extern __shared__ char smem[];
    gemm_tile(Ahi, Alo, Bhi, Blo, C, blockIdx.y * 128, blockIdx.x * 128, smem);
}

// ---------------------------------------------------------------------------
// Tensor-core flash attention (causal), bf16 hi/lo MMAs, fp32 softmax.
// Epilogue writes bf16 hi/lo directly (feeds final GEMM, no split pass).
// ---------------------------------------------------------------------------
#define AP 72
#define ATILE (64 * AP)

__global__ __launch_bounds__(128) void attn_tc()
{
    extern __shared__ __nv_bfloat16 ash[];
    __nv_bfloat16* Qh = ash;
    __nv_bfloat16* Ql = Qh + ATILE;
    __nv_bfloat16* Kh = Ql + ATILE;
    __nv_bfloat16* Kl = Kh + ATILE;
    __nv_bfloat16* Vh = Kl + ATILE;
    __nv_bfloat16* Vl = Vh + ATILE;
    const uint32_t sQh = smem_u32(Qh), sQl = smem_u32(Ql);
    const uint32_t sKh = smem_u32(Kh), sKl = smem_u32(Kl);
    const uint32_t sVh = smem_u32(Vh), sVl = smem_u32(Vl);

    const int tid  = threadIdx.x;
    const int lane = tid & 31;
    const int w    = tid >> 5;
    const int qtile = blockIdx.x;
    const int bh = blockIdx.y;
    const int b = bh / HH, h = bh % HH;
    const int q0 = qtile * 64;

    const float* qptr = g_q + (size_t)b * TT * CC + h * DD;
    const float* kptr = g_k + (size_t)b * TT * CC + h * DD;
    const float* vptr = g_v + (size_t)b * TT * CC + h * DD;

#pragma unroll
    for (int it = 0; it < 8; it++) {
        int lin = tid + it * 128;
        int row = lin >> 4;
        int c4  = (lin & 15) * 4;
        float4 v4 = *(const float4*)&qptr[(size_t)(q0 + row) * CC + c4];
        float f[4] = { v4.x * 0.125f, v4.y * 0.125f, v4.z * 0.125f, v4.w * 0.125f };
        __nv_bfloat16 hh[4], ll[4];
#pragma unroll
        for (int e = 0; e < 4; e++) {
            hh[e] = __float2bfloat16(f[e]);
            ll[e] = __float2bfloat16(f[e] - __bfloat162float(hh[e]));
        }
        *(__nv_bfloat162*)&Qh[row * AP + c4]     = __nv_bfloat162(hh[0], hh[1]);
        *(__nv_bfloat162*)&Qh[row * AP + c4 + 2] = __nv_bfloat162(hh[2], hh[3]);
        *(__nv_bfloat162*)&Ql[row * AP + c4]     = __nv_bfloat162(ll[0], ll[1]);
        *(__nv_bfloat162*)&Ql[row * AP + c4 + 2] = __nv_bfloat162(ll[2], ll[3]);
    }
    __syncthreads();

    uint32_t aqh[4][4], aql[4][4];
    {
        const uint32_t kb = (uint32_t)(lane & 3) * 4u;
        const uint32_t r0 = (uint32_t)(w * 16 + (lane >> 2)) * (AP * 2) + kb;
        const uint32_t r1 = r0 + 8u * (AP * 2);
#pragma unroll
        for (int s = 0; s < 4; s++) {
            uint32_t ko = (uint32_t)s * 32u;
            aqh[s][0] = lds32(sQh + r0 + ko);       aqh[s][1] = lds32(sQh + r1 + ko);
            aqh[s][2] = lds32(sQh + r0 + ko + 16u); aqh[s][3] = lds32(sQh + r1 + ko + 16u);
            aql[s][0] = lds32(sQl + r0 + ko);       aql[s][1] = lds32(sQl + r1 + ko);
            aql[s][2] = lds32(sQl + r0 + ko + 16u); aql[s][3] = lds32(sQl + r1 + ko + 16u);
        }
    }

    float m0r = -1e30f, m1r = -1e30f, l0r = 0.f, l1r = 0.f;
    float ofr[8][4];
#pragma unroll
    for (int j = 0; j < 8; j++)
#pragma unroll
        for (int r = 0; r < 4; r++) ofr[j][r] = 0.f;

    const int r0g = q0 + w * 16 + (lane >> 2);
    const int r1g = r0g + 8;

    const int nkt = qtile + 1;
    for (int kt = 0; kt < nkt; kt++) {
        const int k0 = kt * 64;
        __syncthreads();
#pragma unroll
        for (int it = 0; it < 8; it++) {
            int lin = tid + it * 128;
            int row = lin >> 4;
            int c4  = (lin & 15) * 4;
            float4 kv = *(const float4*)&kptr[(size_t)(k0 + row) * CC + c4];
            float kf[4] = { kv.x, kv.y, kv.z, kv.w };
            __nv_bfloat16 khh[4], kll[4];
#pragma unroll
            for (int e = 0; e < 4; e++) {
                khh[e] = __float2bfloat16(kf[e]);
                kll[e] = __float2bfloat16(kf[e] - __bfloat162float(khh[e]));
            }
            *(__nv_bfloat162*)&Kh[row * AP + c4]     = __nv_bfloat162(khh[0], khh[1]);
            *(__nv_bfloat162*)&Kh[row * AP + c4 + 2] = __nv_bfloat162(khh[2], khh[3]);
            *(__nv_bfloat162*)&Kl[row * AP + c4]     = __nv_bfloat162(kll[0], kll[1]);
            *(__nv_bfloat162*)&Kl[row * AP + c4 + 2] = __nv_bfloat162(kll[2], kll[3]);

            float4 vv = *(const float4*)&vptr[(size_t)(k0 + row) * CC + c4];
            float vf[4] = { vv.x, vv.y, vv.z, vv.w };
#pragma unroll
            for (int e = 0; e < 4; e++) {
                __nv_bfloat16 vh = __float2bfloat16(vf[e]);
                __nv_bfloat16 vl = __float2bfloat16(vf[e] - __bfloat162float(vh));
                Vh[(c4 + e) * AP + row] = vh;
                Vl[(c4 + e) * AP + row] = vl;
            }
        }
        __syncthreads();

        float sfr[8][4];
#pragma unroll
        for (int j = 0; j < 8; j++)
#pragma unroll
            for (int r = 0; r < 4; r++) sfr[j][r] = 0.f;

        const uint32_t kb = (uint32_t)(lane & 3) * 4u;
#pragma unroll
        for (int j = 0; j < 8; j++) {
            uint32_t nrow = (uint32_t)(j * 8 + (lane >> 2)) * (AP * 2) + kb;
#pragma unroll
            for (int s = 0; s < 4; s++) {
                uint32_t ko = (uint32_t)s * 32u;
                uint32_t bhf[2], blf[2];
                bhf[0] = lds32(sKh + nrow + ko); bhf[1] = lds32(sKh + nrow + ko + 16u);
                blf[0] = lds32(sKl + nrow + ko); blf[1] = lds32(sKl + nrow + ko + 16u);
                mma_bf16(sfr[j], aqh[s], bhf);
                mma_bf16(sfr[j], aqh[s], blf);
                mma_bf16(sfr[j], aql[s], bhf);
            }
        }

        if (kt == qtile) {
#pragma unroll
            for (int j = 0; j < 8; j++) {
                int cbase = k0 + j * 8 + 2 * (lane & 3);
                if (cbase > r0g)     sfr[j][0] = -1e30f;
                if (cbase + 1 > r0g) sfr[j][1] = -1e30f;
                if (cbase > r1g)     sfr[j][2] = -1e30f;
                if (cbase + 1 > r1g) sfr[j][3] = -1e30f;
            }
        }

        float mx0 = -1e30f, mx1 = -1e30f;
#pragma unroll
        for (int j = 0; j < 8; j++) {
            mx0 = fmaxf(mx0, fmaxf(sfr[j][0], sfr[j][1]));
            mx1 = fmaxf(mx1, fmaxf(sfr[j][2], sfr[j][3]));
        }
        mx0 = fmaxf(mx0, __shfl_xor_sync(0xffffffffu, mx0, 1));
        mx0 = fmaxf(mx0, __shfl_xor_sync(0xffffffffu, mx0, 2));
        mx1 = fmaxf(mx1, __shfl_xor_sync(0xffffffffu, mx1, 1));
        mx1 = fmaxf(mx1, __shfl_xor_sync(0xffffffffu, mx1, 2));

        float mn0 = fmaxf(m0r, mx0), mn1 = fmaxf(m1r, mx1);
        float corr0 = __expf(m0r - mn0), corr1 = __expf(m1r - mn1);
        m0r = mn0; m1r = mn1;

        float rs0 = 0.f, rs1 = 0.f;
#pragma unroll
        for (int j = 0; j < 8; j++) {
            sfr[j][0] = __expf(sfr[j][0] - mn0);
            sfr[j][1] = __expf(sfr[j][1] - mn0);
            sfr[j][2] = __expf(sfr[j][2] - mn1);
            sfr[j][3] = __expf(sfr[j][3] - mn1);
            rs0 += sfr[j][0] + sfr[j][1];
            rs1 += sfr[j][2] + sfr[j][3];
        }
        rs0 += __shfl_xor_sync(0xffffffffu, rs0, 1);
        rs0 += __shfl_xor_sync(0xffffffffu, rs0, 2);
        rs1 += __shfl_xor_sync(0xffffffffu, rs1, 1);
        rs1 += __shfl_xor_sync(0xffffffffu, rs1, 2);
        l0r = l0r * corr0 + rs0;
        l1r = l1r * corr1 + rs1;

#pragma unroll
        for (int j = 0; j < 8; j++) {
            ofr[j][0] *= corr0; ofr[j][1] *= corr0;
            ofr[j][2] *= corr1; ofr[j][3] *= corr1;
        }

        uint32_t pah[4][4], pal[4][4];
#pragma unroll
        for (int s = 0; s < 4; s++) {
            const int ja = 2 * s, jb = 2 * s + 1;
            float p[8] = { sfr[ja][0], sfr[ja][1], sfr[ja][2], sfr[ja][3],
                           sfr[jb][0], sfr[jb][1], sfr[jb][2], sfr[jb][3] };
            __nv_bfloat16 phh[8];
            float pl[8];
#pragma unroll
            for (int e = 0; e < 8; e++) {
                phh[e] = __float2bfloat16(p[e]);
                pl[e] = p[e] - __bfloat162float(phh[e]);
            }
            pah[s][0] = pack_bf16x2(__bfloat162float(phh[0]), __bfloat162float(phh[1]));
            pah[s][1] = pack_bf16x2(__bfloat162float(phh[2]), __bfloat162float(phh[3]));
            pah[s][2] = pack_bf16x2(__bfloat162float(phh[4]), __bfloat162float(phh[5]));
            pah[s][3] = pack_bf16x2(__bfloat162float(phh[6]), __bfloat162float(phh[7]));
            pal[s][0] = pack_bf16x2(pl[0], pl[1]);
            pal[s][1] = pack_bf16x2(pl[2], pl[3]);
            pal[s][2] = pack_bf16x2(pl[4], pl[5]);
            pal[s][3] = pack_bf16x2(pl[6], pl[7]);
        }

#pragma unroll
        for (int j = 0; j < 8; j++) {
            uint32_t drow = (uint32_t)(j * 8 + (lane >> 2)) * (AP * 2) + kb;
#pragma unroll
            for (int s = 0; s < 4; s++) {
                uint32_t ko = (uint32_t)s * 32u;
                uint32_t bvh[2], bvl[2];
                bvh[0] = lds32(sVh + drow + ko); bvh[1] = lds32(sVh + drow + ko + 16u);
                bvl[0] = lds32(sVl + drow + ko); bvl[1] = lds32(sVl + drow + ko + 16u);
                mma_bf16(ofr[j], pah[s], bvh);
                mma_bf16(ofr[j], pah[s], bvl);
                mma_bf16(ofr[j], pal[s], bvh);
            }
        }
    }

    // Epilogue: normalize, split hi/lo, write bf16 pairs directly
    float inv0 = 1.f / l0r, inv1 = 1.f / l1r;
    __nv_bfloat16* ahp = g_ahi + (size_t)b * TT * CC + h * DD;
    __nv_bfloat16* alp = g_alo + (size_t)b * TT * CC + h * DD;
#pragma unroll
    for (int j = 0; j < 8; j++) {
        int col = j * 8 + 2 * (lane & 3);
        float v0 = ofr[j][0] * inv0, v1 = ofr[j][1] * inv0;
        float v2 = ofr[j][2] * inv1, v3 = ofr[j][3] * inv1;
        __nv_bfloat16 h0 = __float2bfloat16(v0), h1 = __float2bfloat16(v1);
        __nv_bfloat16 h2 = __float2bfloat16(v2), h3 = __float2bfloat16(v3);
        *(uint32_t*)&ahp[(size_t)r0g * CC + col] =
            pack_bf16x2(__bfloat162float(h0), __bfloat162float(h1));
        *(uint32_t*)&alp[(size_t)r0g * CC + col] =
            pack_bf16x2(v0 - __bfloat162float(h0), v1 - __bfloat162float(h1));
        *(uint32_t*)&ahp[(size_t)r1g * CC + col] =
            pack_bf16x2(__bfloat162float(h2), __bfloat162float(h3));
        *(uint32_t*)&alp[(size_t)r1g * CC + col] =
            pack_bf16x2(v2 - __bfloat162float(h2), v3 - __bfloat162float(h3));
    }
}

// ---------------------------------------------------------------------------
extern "C" void kernel_launch(void* const* d_in, const int* in_sizes, int n_in,
                              void* d_out, int out_size)
{
    const float* x   = (const float*)d_in[0];
    const float* W_Q = (const float*)d_in[1];
    const float* W_K = (const float*)d_in[2];
    const float* W_V = (const float*)d_in[3];
    const float* W_O = (const float*)d_in[4];
    float* out = (float*)d_out;

    float *q, *k, *v;
    __nv_bfloat16 *xhi, *xlo, *ahi, *alo, *whi, *wlo;
    cudaGetSymbolAddress((void**)&q,    g_q);
    cudaGetSymbolAddress((void**)&k,    g_k);
    cudaGetSymbolAddress((void**)&v,    g_v);
    cudaGetSymbolAddress((void**)&xhi,  g_xhi);
    cudaGetSymbolAddress((void**)&xlo,  g_xlo);
    cudaGetSymbolAddress((void**)&ahi,  g_ahi);
    cudaGetSymbolAddress((void**)&alo,  g_alo);
    cudaGetSymbolAddress((void**)&whi,  g_whi);
    cudaGetSymbolAddress((void**)&wlo,  g_wlo);

    const int gemm_smem = 2 * 40960;
    cudaFuncSetAttribute(gemm_qkv,
                         cudaFuncAttributeMaxDynamicSharedMemorySize, gemm_smem);
    cudaFuncSetAttribute(gemm_one,
                         cudaFuncAttributeMaxDynamicSharedMemorySize, gemm_smem);
    const int attn_smem = 6 * ATILE * (int)sizeof(__nv_bfloat16);
    cudaFuncSetAttribute(attn_tc,
                         cudaFuncAttributeMaxDynamicSharedMemorySize, attn_smem);

    {
        int n4 = MM * CC / 4;
        split_kernel<<<(n4 + 255) / 256, 256>>>(x, xhi, xlo, n4);
        int w4 = CC * CC / 4;
        split_kernel<<<(w4 + 255) / 256, 256>>>(W_Q, whi + 0 * CC * CC, wlo + 0 * CC * CC, w4);
        split_kernel<<<(w4 + 255) / 256, 256>>>(W_K, whi + 1 * CC * CC, wlo + 1 * CC * CC, w4);
        split_kernel<<<(w4 + 255) / 256, 256>>>(W_V, whi + 2 * CC * CC, wlo + 2 * CC * CC, w4);
        split_kernel<<<(w4 + 255) / 256, 256>>>(W_O, whi + 3 * CC * CC, wlo + 3 * CC * CC, w4);
    }

    dim3 qkvgrid(24, MM / 128);   // (24, 64)
    gemm_qkv<<<qkvgrid, 256, gemm_smem>>>(xhi, xlo, whi, wlo, q, k, v);

    dim3 agrid(TT / 64, BB * HH);
    attn_tc<<<agrid, 128, attn_smem>>>();

    dim3 ogrid(CC / 128, MM / 128);
    gemm_one<<<ogrid, 256, gemm_smem>>>(ahi, alo, whi + 3 * CC * CC, wlo + 3 * CC * CC, out);
}